// round 1
// baseline (speedup 1.0000x reference)
#include <cuda_runtime.h>
#include <math.h>

// ---------------- problem constants ----------------
#define B_      16
#define S_      576
#define F_      700
#define D_      64
#define KC_     1024            // codebook entries
#define T_      (B_*S_)         // 9216 tokens
#define H1_     512
#define H2_     256
#define ENC_    128             // 2*D
#define SF_     (S_*F_)         // 403200
#define SD_     (S_*D_)         // 36864

#define OUT_REC  0
#define OUT_MEAN (B_*SF_)             // 6451200
#define OUT_LV   (OUT_MEAN + T_*D_)   // 7041024
#define OUT_VQL  (OUT_LV + T_*D_)     // 7630848

#define DEC1_CHUNKS 144           // 36864 / 256

// ---------------- scratch (device globals; no allocation allowed) ----------------
__device__ __align__(256) float g_h1[T_*H1_];
__device__ __align__(256) float g_h2[T_*H2_];
__device__ __align__(256) float g_enc[T_*ENC_];
__device__ __align__(256) float g_ze[T_*D_];
__device__ __align__(256) float g_zq[T_*D_];
__device__ __align__(256) float g_cross[T_*KC_];
__device__ __align__(256) float g_csq[KC_];
__device__ __align__(256) float g_tokloss[T_];
__device__ __align__(256) float g_dpart[DEC1_CHUNKS*16*H2_];
__device__ __align__(256) float g_dvec[16*H2_];

__device__ __forceinline__ float softplusf(float x) {
    // jax.nn.softplus = logaddexp(x, 0) = max(x,0) + log1p(exp(-|x|))
    return fmaxf(x, 0.0f) + log1pf(expf(-fabsf(x)));
}

// ---------------- generic NN SGEMM: C = act(A(MxK) * B(KxN) + bias) ----------------
// BM=BN=128, BK=16, 256 threads, 8x8 micro-tile.
template<int ACT>
__global__ __launch_bounds__(256) void sgemm_nn_kernel(
    int M, int N, int K,
    const float* __restrict__ A, const float* __restrict__ Bm,
    const float* __restrict__ bias, float* __restrict__ C)
{
    __shared__ __align__(16) float As[16][128];
    __shared__ __align__(16) float Bs[16][128];

    int tid  = threadIdx.x;
    int row0 = blockIdx.y * 128;
    int col0 = blockIdx.x * 128;

    int ar = tid >> 2;            // 0..63
    int ac = (tid & 3) << 2;      // 0,4,8,12
    int br = tid >> 5;            // 0..7
    int bc = (tid & 31) << 2;     // 0..124
    int trow = tid >> 4;          // 0..15
    int tcol = tid & 15;          // 0..15

    float acc[8][8];
#pragma unroll
    for (int i = 0; i < 8; ++i)
#pragma unroll
        for (int j = 0; j < 8; ++j) acc[i][j] = 0.0f;

    for (int k0 = 0; k0 < K; k0 += 16) {
        // load A tile (transposed into As[k][m]) with K-edge guard
#pragma unroll
        for (int h = 0; h < 2; ++h) {
            int r = ar + (h << 6);
            const float* ap = A + (size_t)(row0 + r) * K + k0 + ac;
            float4 av;
            if (k0 + ac + 3 < K) {
                av = *(const float4*)ap;
            } else {
                av.x = (k0 + ac     < K) ? ap[0] : 0.0f;
                av.y = (k0 + ac + 1 < K) ? ap[1] : 0.0f;
                av.z = (k0 + ac + 2 < K) ? ap[2] : 0.0f;
                av.w = 0.0f;
            }
            As[ac + 0][r] = av.x;
            As[ac + 1][r] = av.y;
            As[ac + 2][r] = av.z;
            As[ac + 3][r] = av.w;

            int rb = br + (h << 3);
            float4 bv = make_float4(0.f, 0.f, 0.f, 0.f);
            if (k0 + rb < K)
                bv = *(const float4*)(Bm + (size_t)(k0 + rb) * N + col0 + bc);
            *(float4*)&Bs[rb][bc] = bv;
        }
        __syncthreads();

#pragma unroll
        for (int k = 0; k < 16; ++k) {
            float a[8], b[8];
            *(float4*)&a[0] = *(const float4*)&As[k][trow * 8];
            *(float4*)&a[4] = *(const float4*)&As[k][trow * 8 + 4];
            *(float4*)&b[0] = *(const float4*)&Bs[k][tcol * 8];
            *(float4*)&b[4] = *(const float4*)&Bs[k][tcol * 8 + 4];
#pragma unroll
            for (int i = 0; i < 8; ++i)
#pragma unroll
                for (int j = 0; j < 8; ++j)
                    acc[i][j] = fmaf(a[i], b[j], acc[i][j]);
        }
        __syncthreads();
    }

    float bb[8];
    *(float4*)&bb[0] = *(const float4*)&bias[col0 + tcol * 8];
    *(float4*)&bb[4] = *(const float4*)&bias[col0 + tcol * 8 + 4];

#pragma unroll
    for (int i = 0; i < 8; ++i) {
        int row = row0 + trow * 8 + i;
        float o[8];
#pragma unroll
        for (int j = 0; j < 8; ++j) {
            float v = acc[i][j] + bb[j];
            o[j] = ACT ? fmaxf(v, 0.0f) : v;
        }
        *(float4*)(C + (size_t)row * N + col0 + tcol * 8)     = *(float4*)&o[0];
        *(float4*)(C + (size_t)row * N + col0 + tcol * 8 + 4) = *(float4*)&o[4];
    }
}

// ---------------- NT SGEMM for VQ cross: C(MxN) = A(MxK) * B(NxK)^T ----------------
// K must be a multiple of 16 (K=64 here).
__global__ __launch_bounds__(256) void sgemm_nt_kernel(
    int M, int N, int K,
    const float* __restrict__ A, const float* __restrict__ Bm,
    float* __restrict__ C)
{
    __shared__ __align__(16) float As[16][128];
    __shared__ __align__(16) float Bs[16][128];

    int tid  = threadIdx.x;
    int row0 = blockIdx.y * 128;
    int col0 = blockIdx.x * 128;

    int ar = tid >> 2;
    int ac = (tid & 3) << 2;
    int trow = tid >> 4;
    int tcol = tid & 15;

    float acc[8][8];
#pragma unroll
    for (int i = 0; i < 8; ++i)
#pragma unroll
        for (int j = 0; j < 8; ++j) acc[i][j] = 0.0f;

    for (int k0 = 0; k0 < K; k0 += 16) {
#pragma unroll
        for (int h = 0; h < 2; ++h) {
            int r = ar + (h << 6);
            float4 av = *(const float4*)(A + (size_t)(row0 + r) * K + k0 + ac);
            As[ac + 0][r] = av.x; As[ac + 1][r] = av.y;
            As[ac + 2][r] = av.z; As[ac + 3][r] = av.w;
            float4 bv = *(const float4*)(Bm + (size_t)(col0 + r) * K + k0 + ac);
            Bs[ac + 0][r] = bv.x; Bs[ac + 1][r] = bv.y;
            Bs[ac + 2][r] = bv.z; Bs[ac + 3][r] = bv.w;
        }
        __syncthreads();
#pragma unroll
        for (int k = 0; k < 16; ++k) {
            float a[8], b[8];
            *(float4*)&a[0] = *(const float4*)&As[k][trow * 8];
            *(float4*)&a[4] = *(const float4*)&As[k][trow * 8 + 4];
            *(float4*)&b[0] = *(const float4*)&Bs[k][tcol * 8];
            *(float4*)&b[4] = *(const float4*)&Bs[k][tcol * 8 + 4];
#pragma unroll
            for (int i = 0; i < 8; ++i)
#pragma unroll
                for (int j = 0; j < 8; ++j)
                    acc[i][j] = fmaf(a[i], b[j], acc[i][j]);
        }
        __syncthreads();
    }

#pragma unroll
    for (int i = 0; i < 8; ++i) {
        int row = row0 + trow * 8 + i;
        *(float4*)(C + (size_t)row * N + col0 + tcol * 8)     = *(float4*)&acc[i][0];
        *(float4*)(C + (size_t)row * N + col0 + tcol * 8 + 4) = *(float4*)&acc[i][4];
    }
}

// ---------------- small kernels ----------------
__global__ void csq_kernel(const float* __restrict__ cb) {
    int k = blockIdx.x * 256 + threadIdx.x;          // grid 4 x 256 = 1024
    const float4* c = (const float4*)cb + k * 16;
    float s = 0.0f;
#pragma unroll
    for (int i = 0; i < 16; ++i) {
        float4 v = c[i];
        s += v.x * v.x + v.y * v.y + v.z * v.z + v.w * v.w;
    }
    g_csq[k] = s;
}

__global__ void reparam_kernel(const float* __restrict__ eps, float* __restrict__ out) {
    int i = blockIdx.x * 256 + threadIdx.x;
    if (i >= T_ * D_) return;
    int t = i >> 6, d = i & 63;
    float m  = g_enc[t * ENC_ + d];
    float lv = g_enc[t * ENC_ + 64 + d];
    float z  = m + expf(0.5f * lv) * eps[i];
    g_ze[i] = z;
    out[OUT_MEAN + i] = m;
    out[OUT_LV + i]   = lv;
}

// warp per token: argmin over 1024 codes of (c_sq - 2*cross), gather code, per-token loss
__global__ __launch_bounds__(256) void argmin_kernel(const float* __restrict__ cb) {
    int t    = (blockIdx.x * 256 + threadIdx.x) >> 5;   // 1152 blocks x 8 warps = 9216
    int lane = threadIdx.x & 31;

    const float4* cr = (const float4*)g_cross + (size_t)t * 256;
    const float4* cq = (const float4*)g_csq;

    float best = 3.4e38f;
    int bestk = 0;
#pragma unroll
    for (int i = 0; i < 8; ++i) {
        int v = lane + i * 32;        // float4 index 0..255
        float4 c = cr[v];
        float4 q = cq[v];
        float s0 = q.x - 2.0f * c.x;
        float s1 = q.y - 2.0f * c.y;
        float s2 = q.z - 2.0f * c.z;
        float s3 = q.w - 2.0f * c.w;
        int kb = v * 4;
        if (s0 < best) { best = s0; bestk = kb;     }
        if (s1 < best) { best = s1; bestk = kb + 1; }
        if (s2 < best) { best = s2; bestk = kb + 2; }
        if (s3 < best) { best = s3; bestk = kb + 3; }
    }
#pragma unroll
    for (int off = 16; off; off >>= 1) {
        float ob = __shfl_down_sync(0xffffffffu, best, off);
        int   ok = __shfl_down_sync(0xffffffffu, bestk, off);
        if (ob < best || (ob == best && ok < bestk)) { best = ob; bestk = ok; }
    }
    bestk = __shfl_sync(0xffffffffu, bestk, 0);

    float l = 0.0f;
    if (lane < 16) {
        float4 cv = ((const float4*)cb)[bestk * 16 + lane];
        float4 zv = ((const float4*)g_ze)[t * 16 + lane];
        ((float4*)g_zq)[t * 16 + lane] = cv;
        float dx = zv.x - cv.x, dy = zv.y - cv.y;
        float dz = zv.z - cv.z, dw = zv.w - cv.w;
        l = dx * dx + dy * dy + dz * dz + dw * dw;
    }
#pragma unroll
    for (int off = 16; off; off >>= 1)
        l += __shfl_down_sync(0xffffffffu, l, off);
    if (lane == 0) g_tokloss[t] = l;
}

// decoder GEMM1 split-K partials: each block handles 256 K-rows, all 16x256 outputs
__global__ __launch_bounds__(256) void dec1_part_kernel(const float* __restrict__ W) {
    __shared__ __align__(16) float zs[256 * 16];   // zs[kk*16 + b]
    int k0 = blockIdx.x * 256;
    for (int i = threadIdx.x; i < 4096; i += 256) {
        int b = i >> 8, kk = i & 255;
        zs[kk * 16 + b] = g_zq[b * SD_ + k0 + kk];
    }
    __syncthreads();

    int n = threadIdx.x;
    float acc[16];
#pragma unroll
    for (int b = 0; b < 16; ++b) acc[b] = 0.0f;

#pragma unroll 8
    for (int kk = 0; kk < 256; ++kk) {
        float w = W[(size_t)(k0 + kk) * H2_ + n];
        const float4* zk = (const float4*)(zs + kk * 16);
        float zv[16];
        *(float4*)&zv[0]  = zk[0];
        *(float4*)&zv[4]  = zk[1];
        *(float4*)&zv[8]  = zk[2];
        *(float4*)&zv[12] = zk[3];
#pragma unroll
        for (int b = 0; b < 16; ++b) acc[b] = fmaf(zv[b], w, acc[b]);
    }
#pragma unroll
    for (int b = 0; b < 16; ++b)
        g_dpart[blockIdx.x * 4096 + b * H2_ + n] = acc[b];
}

__global__ void dec1_fin_kernel(const float* __restrict__ bias) {
    int n = blockIdx.x * 256 + threadIdx.x;   // 16 blocks -> 4096
    float s = 0.0f;
    for (int c = 0; c < DEC1_CHUNKS; ++c) s += g_dpart[c * 4096 + n];
    g_dvec[n] = fmaxf(s + bias[n & 255], 0.0f);
}

__global__ void vqloss_kernel(float* __restrict__ out) {
    __shared__ float sb[256];
    float a = 0.0f;
    for (int i = threadIdx.x; i < T_; i += 256) a += g_tokloss[i];
    sb[threadIdx.x] = a;
    __syncthreads();
    for (int s = 128; s > 0; s >>= 1) {
        if (threadIdx.x < s) sb[threadIdx.x] += sb[threadIdx.x + s];
        __syncthreads();
    }
    if (threadIdx.x == 0) out[OUT_VQL] = sb[0] / (float)(T_ * D_);
}

// decoder GEMM2 + softplus: out[b][n] = softplus(sum_k d[b][k]*W[k][n] + bias[n])
// thread handles 4 columns x 16 batches; W streamed coalesced, d broadcast from smem
__global__ __launch_bounds__(256) void dec2_kernel(
    const float* __restrict__ W, const float* __restrict__ bias,
    float* __restrict__ out)
{
    __shared__ __align__(16) float ds[H2_ * 16];   // ds[k*16 + b]
    for (int i = threadIdx.x; i < 4096; i += 256) {
        int b = i >> 8, k = i & 255;
        ds[k * 16 + b] = g_dvec[i];
    }
    __syncthreads();

    int n = (blockIdx.x * 256 + threadIdx.x) * 4;
    if (n >= SF_) return;

    float4 acc[16];
#pragma unroll
    for (int b = 0; b < 16; ++b) acc[b] = make_float4(0.f, 0.f, 0.f, 0.f);

#pragma unroll 8
    for (int k = 0; k < H2_; ++k) {
        float4 w = *(const float4*)(W + (size_t)k * SF_ + n);
        const float4* dk = (const float4*)(ds + k * 16);
        float dv[16];
        *(float4*)&dv[0]  = dk[0];
        *(float4*)&dv[4]  = dk[1];
        *(float4*)&dv[8]  = dk[2];
        *(float4*)&dv[12] = dk[3];
#pragma unroll
        for (int b = 0; b < 16; ++b) {
            acc[b].x = fmaf(dv[b], w.x, acc[b].x);
            acc[b].y = fmaf(dv[b], w.y, acc[b].y);
            acc[b].z = fmaf(dv[b], w.z, acc[b].z);
            acc[b].w = fmaf(dv[b], w.w, acc[b].w);
        }
    }

    float4 bb = *(const float4*)(bias + n);
#pragma unroll
    for (int b = 0; b < 16; ++b) {
        float4 v;
        v.x = softplusf(acc[b].x + bb.x);
        v.y = softplusf(acc[b].y + bb.y);
        v.z = softplusf(acc[b].z + bb.z);
        v.w = softplusf(acc[b].w + bb.w);
        *(float4*)(out + (size_t)b * SF_ + n) = v;
    }
}

// ---------------- launch ----------------
extern "C" void kernel_launch(void* const* d_in, const int* in_sizes, int n_in,
                              void* d_out, int out_size)
{
    const float* x   = (const float*)d_in[0];
    const float* eps = (const float*)d_in[1];
    const float* We1 = (const float*)d_in[2];
    const float* be1 = (const float*)d_in[3];
    const float* We2 = (const float*)d_in[4];
    const float* be2 = (const float*)d_in[5];
    const float* We3 = (const float*)d_in[6];
    const float* be3 = (const float*)d_in[7];
    const float* cb  = (const float*)d_in[8];
    const float* Wd1 = (const float*)d_in[9];
    const float* bd1 = (const float*)d_in[10];
    const float* Wd2 = (const float*)d_in[11];
    const float* bd2 = (const float*)d_in[12];
    float* out = (float*)d_out;

    void *p_h1, *p_h2, *p_enc, *p_ze, *p_cross;
    cudaGetSymbolAddress(&p_h1,    g_h1);
    cudaGetSymbolAddress(&p_h2,    g_h2);
    cudaGetSymbolAddress(&p_enc,   g_enc);
    cudaGetSymbolAddress(&p_ze,    g_ze);
    cudaGetSymbolAddress(&p_cross, g_cross);

    // codebook squared norms (independent)
    csq_kernel<<<4, 256>>>(cb);

    // encoder MLP
    sgemm_nn_kernel<1><<<dim3(4, 72), 256>>>(T_, H1_, F_,  x,            We1, be1, (float*)p_h1);
    sgemm_nn_kernel<1><<<dim3(2, 72), 256>>>(T_, H2_, H1_, (float*)p_h1, We2, be2, (float*)p_h2);
    sgemm_nn_kernel<0><<<dim3(1, 72), 256>>>(T_, ENC_, H2_,(float*)p_h2, We3, be3, (float*)p_enc);

    // reparameterize + emit mean / log_var
    reparam_kernel<<<(T_ * D_ + 255) / 256, 256>>>(eps, out);

    // VQ: cross = z_e @ codebook^T, then argmin + gather + per-token loss
    sgemm_nt_kernel<<<dim3(8, 72), 256>>>(T_, KC_, D_, (float*)p_ze, cb, (float*)p_cross);
    argmin_kernel<<<T_ / 8, 256>>>(cb);

    // decoder
    dec1_part_kernel<<<DEC1_CHUNKS, 256>>>(Wd1);
    dec1_fin_kernel<<<16, 256>>>(bd1);
    vqloss_kernel<<<1, 256>>>(out);
    dec2_kernel<<<(SF_ / 4 + 255) / 256, 256>>>(Wd2, bd2, out);
}

// round 2
// speedup vs baseline: 1.1103x; 1.1103x over previous
#include <cuda_runtime.h>
#include <math.h>

// ---------------- problem constants ----------------
#define B_      16
#define S_      576
#define F_      700
#define D_      64
#define KC_     1024
#define T_      (B_*S_)         // 9216 tokens
#define H1_     512
#define H2_     256
#define ENC_    128             // 2*D
#define SF_     (S_*F_)         // 403200
#define SD_     (S_*D_)         // 36864
#define ZSPLIT  4

#define OUT_REC  0
#define OUT_MEAN (B_*SF_)
#define OUT_LV   (OUT_MEAN + T_*D_)
#define OUT_VQL  (OUT_LV + T_*D_)

#define DEC1_CHUNKS 144

typedef unsigned long long u64;

// ---------------- scratch (device globals; no allocation allowed) ----------------
__device__ __align__(256) float g_h1[T_*H1_];
__device__ __align__(256) float g_h2[T_*H2_];
__device__ __align__(256) float g_encp[ZSPLIT*T_*ENC_];
__device__ __align__(256) float g_ze[T_*D_];
__device__ __align__(256) float g_zq[T_*D_];
__device__ __align__(256) float g_cross[T_*KC_];
__device__ __align__(256) float g_csq[KC_];
__device__ __align__(256) float g_tokloss[T_];
__device__ __align__(256) float g_dpart[DEC1_CHUNKS*16*H2_];
__device__ __align__(256) float g_dvec[16*H2_];

// ---------------- f32x2 helpers ----------------
__device__ __forceinline__ u64 dupf(float a) {
    unsigned r = __float_as_uint(a);
    u64 d;
    asm("mov.b64 %0, {%1, %1};" : "=l"(d) : "r"(r));
    return d;
}
__device__ __forceinline__ void ffma2(u64 &d, u64 a, u64 b) {
    asm("fma.rn.f32x2 %0, %1, %2, %0;" : "+l"(d) : "l"(a), "l"(b));
}
__device__ __forceinline__ float2 unpk(u64 v) {
    unsigned lo, hi;
    asm("mov.b64 {%0, %1}, %2;" : "=r"(lo), "=r"(hi) : "l"(v));
    return make_float2(__uint_as_float(lo), __uint_as_float(hi));
}

__device__ __forceinline__ float softplusf(float x) {
    return fmaxf(x, 0.0f) + log1pf(expf(-fabsf(x)));
}

// ---------------- NN SGEMM (f32x2): C = act(A(MxK)*B(KxN) + bias) ----------------
// ACT: 0 = bias only, 1 = bias+relu, 2 = raw split-K partial (no bias, offset by blockIdx.z)
template<int ACT>
__global__ __launch_bounds__(256, 2) void sgemm_nn_kernel(
    int M, int N, int K, int kc,
    const float* __restrict__ A, const float* __restrict__ Bm,
    const float* __restrict__ bias, float* __restrict__ C)
{
    __shared__ __align__(16) float As[16][128];
    __shared__ __align__(16) float Bs[16][128];

    int tid  = threadIdx.x;
    int row0 = blockIdx.y * 128;
    int col0 = blockIdx.x * 128;
    int z    = blockIdx.z;
    int kStart = z * kc;
    int kEnd   = min(kStart + kc, K);

    int ar = tid >> 2;            // 0..63
    int ac = (tid & 3) << 2;      // 0,4,8,12
    int br = tid >> 5;            // 0..7
    int bc = (tid & 31) << 2;     // 0..124
    int trow = tid >> 4;          // 0..15
    int tcol = tid & 15;          // 0..15

    u64 acc[8][4];
#pragma unroll
    for (int i = 0; i < 8; ++i)
#pragma unroll
        for (int j = 0; j < 4; ++j) acc[i][j] = 0ULL;

    for (int k0 = kStart; k0 < kEnd; k0 += 16) {
#pragma unroll
        for (int h = 0; h < 2; ++h) {
            int r = ar + (h << 6);
            const float* ap = A + (size_t)(row0 + r) * K + k0 + ac;
            float4 av;
            if (k0 + ac + 3 < kEnd) {
                av = *(const float4*)ap;
            } else {
                av.x = (k0 + ac     < kEnd) ? ap[0] : 0.0f;
                av.y = (k0 + ac + 1 < kEnd) ? ap[1] : 0.0f;
                av.z = (k0 + ac + 2 < kEnd) ? ap[2] : 0.0f;
                av.w = 0.0f;
            }
            As[ac + 0][r] = av.x;
            As[ac + 1][r] = av.y;
            As[ac + 2][r] = av.z;
            As[ac + 3][r] = av.w;

            int rb = br + (h << 3);
            float4 bv = make_float4(0.f, 0.f, 0.f, 0.f);
            if (k0 + rb < kEnd)
                bv = *(const float4*)(Bm + (size_t)(k0 + rb) * N + col0 + bc);
            *(float4*)&Bs[rb][bc] = bv;
        }
        __syncthreads();

#pragma unroll
        for (int k = 0; k < 16; ++k) {
            float a[8];
            *(float4*)&a[0] = *(const float4*)&As[k][trow * 8];
            *(float4*)&a[4] = *(const float4*)&As[k][trow * 8 + 4];
            u64 ad[8];
#pragma unroll
            for (int i = 0; i < 8; ++i) ad[i] = dupf(a[i]);
            ulonglong2 b0 = *(const ulonglong2*)&Bs[k][tcol * 8];
            ulonglong2 b1 = *(const ulonglong2*)&Bs[k][tcol * 8 + 4];
            u64 b[4] = {b0.x, b0.y, b1.x, b1.y};
#pragma unroll
            for (int i = 0; i < 8; ++i)
#pragma unroll
                for (int j = 0; j < 4; ++j)
                    ffma2(acc[i][j], ad[i], b[j]);
        }
        __syncthreads();
    }

    float bb[8];
    if (ACT != 2) {
        *(float4*)&bb[0] = *(const float4*)&bias[col0 + tcol * 8];
        *(float4*)&bb[4] = *(const float4*)&bias[col0 + tcol * 8 + 4];
    }

    float* Cz = (ACT == 2) ? (C + (size_t)z * M * N) : C;
#pragma unroll
    for (int i = 0; i < 8; ++i) {
        int row = row0 + trow * 8 + i;
        float o[8];
#pragma unroll
        for (int j = 0; j < 4; ++j) {
            float2 f = unpk(acc[i][j]);
            if (ACT == 2) {
                o[2*j]   = f.x;
                o[2*j+1] = f.y;
            } else {
                float v0 = f.x + bb[2*j];
                float v1 = f.y + bb[2*j+1];
                o[2*j]   = (ACT == 1) ? fmaxf(v0, 0.0f) : v0;
                o[2*j+1] = (ACT == 1) ? fmaxf(v1, 0.0f) : v1;
            }
        }
        *(float4*)(Cz + (size_t)row * N + col0 + tcol * 8)     = *(float4*)&o[0];
        *(float4*)(Cz + (size_t)row * N + col0 + tcol * 8 + 4) = *(float4*)&o[4];
    }
}

// ---------------- NT SGEMM (f32x2): C(MxN) = A(MxK) * B(NxK)^T, K mult of 16 ------
__global__ __launch_bounds__(256, 2) void sgemm_nt_kernel(
    int M, int N, int K,
    const float* __restrict__ A, const float* __restrict__ Bm,
    float* __restrict__ C)
{
    __shared__ __align__(16) float As[16][128];
    __shared__ __align__(16) float Bs[16][128];

    int tid  = threadIdx.x;
    int row0 = blockIdx.y * 128;
    int col0 = blockIdx.x * 128;

    int ar = tid >> 2;
    int ac = (tid & 3) << 2;
    int trow = tid >> 4;
    int tcol = tid & 15;

    u64 acc[8][4];
#pragma unroll
    for (int i = 0; i < 8; ++i)
#pragma unroll
        for (int j = 0; j < 4; ++j) acc[i][j] = 0ULL;

    for (int k0 = 0; k0 < K; k0 += 16) {
#pragma unroll
        for (int h = 0; h < 2; ++h) {
            int r = ar + (h << 6);
            float4 av = *(const float4*)(A + (size_t)(row0 + r) * K + k0 + ac);
            As[ac + 0][r] = av.x; As[ac + 1][r] = av.y;
            As[ac + 2][r] = av.z; As[ac + 3][r] = av.w;
            float4 bv = *(const float4*)(Bm + (size_t)(col0 + r) * K + k0 + ac);
            Bs[ac + 0][r] = bv.x; Bs[ac + 1][r] = bv.y;
            Bs[ac + 2][r] = bv.z; Bs[ac + 3][r] = bv.w;
        }
        __syncthreads();
#pragma unroll
        for (int k = 0; k < 16; ++k) {
            float a[8];
            *(float4*)&a[0] = *(const float4*)&As[k][trow * 8];
            *(float4*)&a[4] = *(const float4*)&As[k][trow * 8 + 4];
            u64 ad[8];
#pragma unroll
            for (int i = 0; i < 8; ++i) ad[i] = dupf(a[i]);
            ulonglong2 b0 = *(const ulonglong2*)&Bs[k][tcol * 8];
            ulonglong2 b1 = *(const ulonglong2*)&Bs[k][tcol * 8 + 4];
            u64 b[4] = {b0.x, b0.y, b1.x, b1.y};
#pragma unroll
            for (int i = 0; i < 8; ++i)
#pragma unroll
                for (int j = 0; j < 4; ++j)
                    ffma2(acc[i][j], ad[i], b[j]);
        }
        __syncthreads();
    }

#pragma unroll
    for (int i = 0; i < 8; ++i) {
        int row = row0 + trow * 8 + i;
        float o[8];
#pragma unroll
        for (int j = 0; j < 4; ++j) {
            float2 f = unpk(acc[i][j]);
            o[2*j] = f.x; o[2*j+1] = f.y;
        }
        *(float4*)(C + (size_t)row * N + col0 + tcol * 8)     = *(float4*)&o[0];
        *(float4*)(C + (size_t)row * N + col0 + tcol * 8 + 4) = *(float4*)&o[4];
    }
}

// ---------------- small kernels ----------------
__global__ void csq_kernel(const float* __restrict__ cb) {
    int k = blockIdx.x * 256 + threadIdx.x;
    const float4* c = (const float4*)cb + k * 16;
    float s = 0.0f;
#pragma unroll
    for (int i = 0; i < 16; ++i) {
        float4 v = c[i];
        s += v.x * v.x + v.y * v.y + v.z * v.z + v.w * v.w;
    }
    g_csq[k] = s;
}

// combine split-K partials + bias, emit mean/logvar and z_e
__global__ void reparam_kernel(const float* __restrict__ eps,
                               const float* __restrict__ be3,
                               float* __restrict__ out) {
    int i = blockIdx.x * 256 + threadIdx.x;
    if (i >= T_ * D_) return;
    int t = i >> 6, d = i & 63;
    float m  = be3[d];
    float lv = be3[64 + d];
#pragma unroll
    for (int z = 0; z < ZSPLIT; ++z) {
        m  += g_encp[(size_t)z * T_ * ENC_ + t * ENC_ + d];
        lv += g_encp[(size_t)z * T_ * ENC_ + t * ENC_ + 64 + d];
    }
    float zv = m + expf(0.5f * lv) * eps[i];
    g_ze[i] = zv;
    out[OUT_MEAN + i] = m;
    out[OUT_LV + i]   = lv;
}

// warp per token: argmin over 1024 codes of (c_sq - 2*cross), gather, per-token loss
__global__ __launch_bounds__(256) void argmin_kernel(const float* __restrict__ cb) {
    int t    = (blockIdx.x * 256 + threadIdx.x) >> 5;
    int lane = threadIdx.x & 31;

    const float4* cr = (const float4*)g_cross + (size_t)t * 256;
    const float4* cq = (const float4*)g_csq;

    float best = 3.4e38f;
    int bestk = 0;
#pragma unroll
    for (int i = 0; i < 8; ++i) {
        int v = lane + i * 32;
        float4 c = cr[v];
        float4 q = cq[v];
        float s0 = q.x - 2.0f * c.x;
        float s1 = q.y - 2.0f * c.y;
        float s2 = q.z - 2.0f * c.z;
        float s3 = q.w - 2.0f * c.w;
        int kb = v * 4;
        if (s0 < best) { best = s0; bestk = kb;     }
        if (s1 < best) { best = s1; bestk = kb + 1; }
        if (s2 < best) { best = s2; bestk = kb + 2; }
        if (s3 < best) { best = s3; bestk = kb + 3; }
    }
#pragma unroll
    for (int off = 16; off; off >>= 1) {
        float ob = __shfl_down_sync(0xffffffffu, best, off);
        int   ok = __shfl_down_sync(0xffffffffu, bestk, off);
        if (ob < best || (ob == best && ok < bestk)) { best = ob; bestk = ok; }
    }
    bestk = __shfl_sync(0xffffffffu, bestk, 0);

    float l = 0.0f;
    if (lane < 16) {
        float4 cv = ((const float4*)cb)[bestk * 16 + lane];
        float4 zv = ((const float4*)g_ze)[t * 16 + lane];
        ((float4*)g_zq)[t * 16 + lane] = cv;
        float dx = zv.x - cv.x, dy = zv.y - cv.y;
        float dz = zv.z - cv.z, dw = zv.w - cv.w;
        l = dx * dx + dy * dy + dz * dz + dw * dw;
    }
#pragma unroll
    for (int off = 16; off; off >>= 1)
        l += __shfl_down_sync(0xffffffffu, l, off);
    if (lane == 0) g_tokloss[t] = l;
}

// decoder GEMM1 split-K partials (f32x2 across batch pairs)
__global__ __launch_bounds__(256) void dec1_part_kernel(const float* __restrict__ W) {
    __shared__ __align__(16) float zs[256 * 16];   // zs[kk*16 + b]
    int k0 = blockIdx.x * 256;
    for (int i = threadIdx.x; i < 4096; i += 256) {
        int b = i >> 8, kk = i & 255;
        zs[kk * 16 + b] = g_zq[b * SD_ + k0 + kk];
    }
    __syncthreads();

    int n = threadIdx.x;
    u64 acc[8];
#pragma unroll
    for (int b2 = 0; b2 < 8; ++b2) acc[b2] = 0ULL;

#pragma unroll 4
    for (int kk = 0; kk < 256; ++kk) {
        u64 wd = dupf(W[(size_t)(k0 + kk) * H2_ + n]);
        const ulonglong2* dk = (const ulonglong2*)(zs + kk * 16);
        ulonglong2 p0 = dk[0], p1 = dk[1], p2 = dk[2], p3 = dk[3];
        u64 dp[8] = {p0.x, p0.y, p1.x, p1.y, p2.x, p2.y, p3.x, p3.y};
#pragma unroll
        for (int b2 = 0; b2 < 8; ++b2) ffma2(acc[b2], dp[b2], wd);
    }
#pragma unroll
    for (int b2 = 0; b2 < 8; ++b2) {
        float2 f = unpk(acc[b2]);
        g_dpart[blockIdx.x * 4096 + (2*b2)   * H2_ + n] = f.x;
        g_dpart[blockIdx.x * 4096 + (2*b2+1) * H2_ + n] = f.y;
    }
}

__global__ void dec1_fin_kernel(const float* __restrict__ bias) {
    int n = blockIdx.x * 256 + threadIdx.x;
    float s = 0.0f;
    for (int c = 0; c < DEC1_CHUNKS; ++c) s += g_dpart[c * 4096 + n];
    g_dvec[n] = fmaxf(s + bias[n & 255], 0.0f);
}

__global__ void vqloss_kernel(float* __restrict__ out) {
    __shared__ float sb[256];
    float a = 0.0f;
    for (int i = threadIdx.x; i < T_; i += 256) a += g_tokloss[i];
    sb[threadIdx.x] = a;
    __syncthreads();
    for (int s = 128; s > 0; s >>= 1) {
        if (threadIdx.x < s) sb[threadIdx.x] += sb[threadIdx.x + s];
        __syncthreads();
    }
    if (threadIdx.x == 0) out[OUT_VQL] = sb[0] / (float)(T_ * D_);
}

// decoder GEMM2 + softplus (f32x2 across batch pairs): W streamed, HBM-bound
__global__ __launch_bounds__(256, 2) void dec2_kernel(
    const float* __restrict__ W, const float* __restrict__ bias,
    float* __restrict__ out)
{
    __shared__ __align__(16) float ds[H2_ * 16];   // ds[k*16 + b]
    for (int i = threadIdx.x; i < 4096; i += 256) {
        int b = i >> 8, k = i & 255;
        ds[k * 16 + b] = g_dvec[i];
    }
    __syncthreads();

    int n = (blockIdx.x * 256 + threadIdx.x) * 4;
    if (n >= SF_) return;

    u64 acc[8][4];
#pragma unroll
    for (int b2 = 0; b2 < 8; ++b2)
#pragma unroll
        for (int c = 0; c < 4; ++c) acc[b2][c] = 0ULL;

#pragma unroll 4
    for (int k = 0; k < H2_; ++k) {
        float4 w = *(const float4*)(W + (size_t)k * SF_ + n);
        u64 wd[4] = {dupf(w.x), dupf(w.y), dupf(w.z), dupf(w.w)};
        const ulonglong2* dk = (const ulonglong2*)(ds + k * 16);
        ulonglong2 p0 = dk[0], p1 = dk[1], p2 = dk[2], p3 = dk[3];
        u64 dp[8] = {p0.x, p0.y, p1.x, p1.y, p2.x, p2.y, p3.x, p3.y};
#pragma unroll
        for (int b2 = 0; b2 < 8; ++b2)
#pragma unroll
            for (int c = 0; c < 4; ++c)
                ffma2(acc[b2][c], dp[b2], wd[c]);
    }

    float4 bb = *(const float4*)(bias + n);
#pragma unroll
    for (int b2 = 0; b2 < 8; ++b2) {
        float2 f0 = unpk(acc[b2][0]);
        float2 f1 = unpk(acc[b2][1]);
        float2 f2 = unpk(acc[b2][2]);
        float2 f3 = unpk(acc[b2][3]);
        float4 v0, v1;
        v0.x = softplusf(f0.x + bb.x);
        v0.y = softplusf(f1.x + bb.y);
        v0.z = softplusf(f2.x + bb.z);
        v0.w = softplusf(f3.x + bb.w);
        v1.x = softplusf(f0.y + bb.x);
        v1.y = softplusf(f1.y + bb.y);
        v1.z = softplusf(f2.y + bb.z);
        v1.w = softplusf(f3.y + bb.w);
        *(float4*)(out + (size_t)(2*b2)   * SF_ + n) = v0;
        *(float4*)(out + (size_t)(2*b2+1) * SF_ + n) = v1;
    }
}

// ---------------- launch ----------------
extern "C" void kernel_launch(void* const* d_in, const int* in_sizes, int n_in,
                              void* d_out, int out_size)
{
    const float* x   = (const float*)d_in[0];
    const float* eps = (const float*)d_in[1];
    const float* We1 = (const float*)d_in[2];
    const float* be1 = (const float*)d_in[3];
    const float* We2 = (const float*)d_in[4];
    const float* be2 = (const float*)d_in[5];
    const float* We3 = (const float*)d_in[6];
    const float* be3 = (const float*)d_in[7];
    const float* cb  = (const float*)d_in[8];
    const float* Wd1 = (const float*)d_in[9];
    const float* bd1 = (const float*)d_in[10];
    const float* Wd2 = (const float*)d_in[11];
    const float* bd2 = (const float*)d_in[12];
    float* out = (float*)d_out;

    void *p_h1, *p_h2, *p_encp, *p_ze, *p_cross;
    cudaGetSymbolAddress(&p_h1,    g_h1);
    cudaGetSymbolAddress(&p_h2,    g_h2);
    cudaGetSymbolAddress(&p_encp,  g_encp);
    cudaGetSymbolAddress(&p_ze,    g_ze);
    cudaGetSymbolAddress(&p_cross, g_cross);

    csq_kernel<<<4, 256>>>(cb);

    // encoder MLP (f32x2)
    sgemm_nn_kernel<1><<<dim3(4, 72, 1), 256>>>(T_, H1_, F_,  F_,  x,            We1, be1, (float*)p_h1);
    sgemm_nn_kernel<1><<<dim3(2, 72, 1), 256>>>(T_, H2_, H1_, H1_, (float*)p_h1, We2, be2, (float*)p_h2);
    // GEMM3 split-K over 4 chunks of 64
    sgemm_nn_kernel<2><<<dim3(1, 72, ZSPLIT), 256>>>(T_, ENC_, H2_, H2_/ZSPLIT,
                                                     (float*)p_h2, We3, nullptr, (float*)p_encp);

    // combine partials + bias + reparameterize
    reparam_kernel<<<(T_ * D_ + 255) / 256, 256>>>(eps, be3, out);

    // VQ
    sgemm_nt_kernel<<<dim3(8, 72), 256>>>(T_, KC_, D_, (float*)p_ze, cb, (float*)p_cross);
    argmin_kernel<<<T_ / 8, 256>>>(cb);

    // decoder
    dec1_part_kernel<<<DEC1_CHUNKS, 256>>>(Wd1);
    dec1_fin_kernel<<<16, 256>>>(bd1);
    vqloss_kernel<<<1, 256>>>(out);
    dec2_kernel<<<(SF_ / 4 + 255) / 256, 256>>>(Wd2, bd2, out);
}

// round 4
// speedup vs baseline: 1.7244x; 1.5531x over previous
#include <cuda_runtime.h>
#include <cuda_bf16.h>
#include <math.h>
#include <stdint.h>

// ---------------- problem constants ----------------
#define B_      16
#define S_      576
#define F_      700
#define D_      64
#define KC_     1024
#define T_      (B_*S_)         // 9216 tokens
#define H1_     512
#define H2_     256
#define ENC_    128             // 2*D
#define SF_     (S_*F_)         // 403200
#define SD_     (S_*D_)         // 36864
#define ZSPLIT  2

#define OUT_REC  0
#define OUT_MEAN (B_*SF_)
#define OUT_LV   (OUT_MEAN + T_*D_)
#define OUT_VQL  (OUT_LV + T_*D_)

#define DEC1_CHUNKS 144

typedef unsigned long long u64;

// ---------------- scratch (device globals; no allocation allowed) ----------------
__device__ __align__(256) float g_h1[T_*H1_];
__device__ __align__(256) float g_h2[T_*H2_];
__device__ __align__(256) float g_encp[ZSPLIT*T_*ENC_];
__device__ __align__(256) float g_ze[T_*D_];
__device__ __align__(256) float g_zq[T_*D_];
__device__ __align__(256) float g_cross[T_*KC_];
__device__ __align__(256) float g_csq[KC_];
__device__ __align__(256) float g_tokloss[T_];
__device__ __align__(256) float g_dpart[DEC1_CHUNKS*16*H2_];
__device__ __align__(256) float g_dvec[16*H2_];
__device__ __align__(256) float g_wt1[H1_*F_];     // We1^T  [512][700]
__device__ __align__(256) float g_wt2[H2_*H1_];    // We2^T  [256][512]
__device__ __align__(256) float g_wt3[ENC_*H2_];   // We3^T  [128][256]

// ---------------- f32x2 helpers (decoder kernels) ----------------
__device__ __forceinline__ u64 dupf(float a) {
    unsigned r = __float_as_uint(a);
    u64 d;
    asm("mov.b64 %0, {%1, %1};" : "=l"(d) : "r"(r));
    return d;
}
__device__ __forceinline__ void ffma2(u64 &d, u64 a, u64 b) {
    asm("fma.rn.f32x2 %0, %1, %2, %0;" : "+l"(d) : "l"(a), "l"(b));
}
__device__ __forceinline__ float2 unpk(u64 v) {
    unsigned lo, hi;
    asm("mov.b64 {%0, %1}, %2;" : "=r"(lo), "=r"(hi) : "l"(v));
    return make_float2(__uint_as_float(lo), __uint_as_float(hi));
}
__device__ __forceinline__ float softplusf(float x) {
    return fmaxf(x, 0.0f) + log1pf(expf(-fabsf(x)));
}

// ---------------- mma.sync helpers (baseline sm_103 tensor path) ----------------
__device__ __forceinline__ uint32_t smem_u32(const void* p) {
    uint32_t a;
    asm("{ .reg .u64 t; cvta.to.shared.u64 t, %1; cvt.u32.u64 %0, t; }" : "=r"(a) : "l"(p));
    return a;
}
__device__ __forceinline__ void ldsm4(uint32_t (&r)[4], uint32_t addr) {
    asm volatile("ldmatrix.sync.aligned.m8n8.x4.shared.b16 {%0,%1,%2,%3}, [%4];"
                 : "=r"(r[0]), "=r"(r[1]), "=r"(r[2]), "=r"(r[3]) : "r"(addr));
}
__device__ __forceinline__ void mma_bf16(float (&d)[4], const uint32_t (&a)[4],
                                         uint32_t b0, uint32_t b1) {
    asm volatile("mma.sync.aligned.m16n8k16.row.col.f32.bf16.bf16.f32 "
                 "{%0,%1,%2,%3}, {%4,%5,%6,%7}, {%8,%9}, {%0,%1,%2,%3};"
                 : "+f"(d[0]), "+f"(d[1]), "+f"(d[2]), "+f"(d[3])
                 : "r"(a[0]), "r"(a[1]), "r"(a[2]), "r"(a[3]), "r"(b0), "r"(b1));
}
// split fp32 pair -> packed bf16x2 hi and lo
__device__ __forceinline__ void split2(float x, float y, uint32_t &hi, uint32_t &lo) {
    __nv_bfloat162 h = __floats2bfloat162_rn(x, y);
    float hx = __bfloat162float(h.x), hy = __bfloat162float(h.y);
    __nv_bfloat162 l = __floats2bfloat162_rn(x - hx, y - hy);
    hi = *reinterpret_cast<uint32_t*>(&h);
    lo = *reinterpret_cast<uint32_t*>(&l);
}

// SMEM layout (bf16 elems), per stage of 20480 elems (40960 B):
//   Ah: [128][40] pad rows (5120)   Al: +5120   Bh: +10240   Bl: +15360
// Row pad 40 elems = 80 B -> conflict-free ldmatrix.
#define STAGE_E   20480
#define SMEM_BYTES (2 * STAGE_E * 2)

// ---------------- bf16x3 tensor-core GEMM: C = act(A(MxK) * Bt(NxK)^T + bias) ------
// BM=128, BN=128, BK=32; 256 threads, warp grid 4(M) x 2(N), warp tile 32x64.
template<int ACT, int HASBIAS, int SPLITK>
__global__ __launch_bounds__(256, 1) void mma_gemm(
    int M, int N, int K, int kPerZ,
    const float* __restrict__ A, const float* __restrict__ Bt,
    const float* __restrict__ bias, float* __restrict__ C)
{
    extern __shared__ __align__(16) __nv_bfloat16 sm[];
    const int tid  = threadIdx.x;
    const int wid  = tid >> 5;
    const int lane = tid & 31;
    const int row0 = blockIdx.y * 128;
    const int col0 = blockIdx.x * 128;
    const int kStart = SPLITK ? blockIdx.z * kPerZ : 0;
    const int kEnd   = SPLITK ? min(kStart + kPerZ, K) : K;
    const int NS = (kEnd - kStart + 31) >> 5;
    const uint32_t smb = smem_u32(sm);

    float acc[2][8][4];
#pragma unroll
    for (int mt = 0; mt < 2; ++mt)
#pragma unroll
        for (int nt = 0; nt < 8; ++nt)
#pragma unroll
            for (int q = 0; q < 4; ++q) acc[mt][nt][q] = 0.0f;

    const int lrow = tid >> 3;        // 0..31 base row (with +32*i)
    const int lc4  = tid & 7;         // float4 col within BK

    float4 pa[4], pb[4];

    // ---- prefetch stage 0 ----
    {
        int k0 = kStart;
#pragma unroll
        for (int i = 0; i < 4; ++i) {
            int row = lrow + i * 32;
            int kk  = k0 + lc4 * 4;
            if (kk < kEnd) {
                pa[i] = *(const float4*)(A  + (size_t)(row0 + row) * K + kk);
                pb[i] = *(const float4*)(Bt + (size_t)(col0 + row) * K + kk);
            } else {
                pa[i] = make_float4(0.f, 0.f, 0.f, 0.f);
                pb[i] = make_float4(0.f, 0.f, 0.f, 0.f);
            }
        }
    }
    // ---- store stage 0 ----
    {
        uint32_t stg = 0;
#pragma unroll
        for (int i = 0; i < 4; ++i) {
            int row = lrow + i * 32;
            uint32_t off = stg + row * 40 + lc4 * 4;
            uint32_t h0, l0, h1, l1;
            split2(pa[i].x, pa[i].y, h0, l0);
            split2(pa[i].z, pa[i].w, h1, l1);
            *(uint2*)&sm[off]          = make_uint2(h0, h1);
            *(uint2*)&sm[off + 5120]   = make_uint2(l0, l1);
            split2(pb[i].x, pb[i].y, h0, l0);
            split2(pb[i].z, pb[i].w, h1, l1);
            *(uint2*)&sm[off + 10240]  = make_uint2(h0, h1);
            *(uint2*)&sm[off + 15360]  = make_uint2(l0, l1);
        }
    }
    __syncthreads();

    const int wm = wid >> 1, wn = wid & 1;
    const int arow  = wm * 32 + (lane & 15);
    const int acolB = (lane >> 4) * 16;                 // byte offset of 8-elem col block
    const int brow  = wn * 64 + ((lane >> 4) << 3) + (lane & 7);
    const int bkhB  = ((lane >> 3) & 1) * 16;           // byte offset of k-half

    for (int s = 0; s < NS; ++s) {
        // prefetch next stage
        if (s + 1 < NS) {
            int k0 = kStart + (s + 1) * 32;
#pragma unroll
            for (int i = 0; i < 4; ++i) {
                int row = lrow + i * 32;
                int kk  = k0 + lc4 * 4;
                if (kk < kEnd) {
                    pa[i] = *(const float4*)(A  + (size_t)(row0 + row) * K + kk);
                    pb[i] = *(const float4*)(Bt + (size_t)(col0 + row) * K + kk);
                } else {
                    pa[i] = make_float4(0.f, 0.f, 0.f, 0.f);
                    pb[i] = make_float4(0.f, 0.f, 0.f, 0.f);
                }
            }
        }

        // compute current stage
        const uint32_t stgB = (uint32_t)(s & 1) * (STAGE_E * 2);
#pragma unroll
        for (int ks = 0; ks < 2; ++ks) {
            uint32_t ah[2][4], al[2][4];
#pragma unroll
            for (int mt = 0; mt < 2; ++mt) {
                uint32_t addr = smb + stgB + (uint32_t)(arow + mt * 16) * 80u
                              + (uint32_t)ks * 32u + acolB;
                ldsm4(ah[mt], addr);
                ldsm4(al[mt], addr + 10240u);
            }
            uint32_t bh[8][2], bl[8][2];
#pragma unroll
            for (int p = 0; p < 4; ++p) {
                uint32_t addr = smb + stgB + 20480u + (uint32_t)(brow + p * 16) * 80u
                              + (uint32_t)ks * 32u + bkhB;
                uint32_t r[4];
                ldsm4(r, addr);
                bh[2*p][0] = r[0]; bh[2*p][1] = r[1];
                bh[2*p+1][0] = r[2]; bh[2*p+1][1] = r[3];
                ldsm4(r, addr + 10240u);
                bl[2*p][0] = r[0]; bl[2*p][1] = r[1];
                bl[2*p+1][0] = r[2]; bl[2*p+1][1] = r[3];
            }
#pragma unroll
            for (int mt = 0; mt < 2; ++mt)
#pragma unroll
                for (int nt = 0; nt < 8; ++nt) {
                    mma_bf16(acc[mt][nt], ah[mt], bh[nt][0], bh[nt][1]);
                    mma_bf16(acc[mt][nt], ah[mt], bl[nt][0], bl[nt][1]);
                    mma_bf16(acc[mt][nt], al[mt], bh[nt][0], bh[nt][1]);
                }
        }

        // store next stage
        if (s + 1 < NS) {
            __syncthreads();
            uint32_t stg = (uint32_t)((s + 1) & 1) * STAGE_E;
#pragma unroll
            for (int i = 0; i < 4; ++i) {
                int row = lrow + i * 32;
                uint32_t off = stg + row * 40 + lc4 * 4;
                uint32_t h0, l0, h1, l1;
                split2(pa[i].x, pa[i].y, h0, l0);
                split2(pa[i].z, pa[i].w, h1, l1);
                *(uint2*)&sm[off]          = make_uint2(h0, h1);
                *(uint2*)&sm[off + 5120]   = make_uint2(l0, l1);
                split2(pb[i].x, pb[i].y, h0, l0);
                split2(pb[i].z, pb[i].w, h1, l1);
                *(uint2*)&sm[off + 10240]  = make_uint2(h0, h1);
                *(uint2*)&sm[off + 15360]  = make_uint2(l0, l1);
            }
            __syncthreads();
        }
    }

    // ---- epilogue ----
    float* Co = SPLITK ? (C + (size_t)blockIdx.z * M * N) : C;
#pragma unroll
    for (int mt = 0; mt < 2; ++mt) {
        int r = row0 + wm * 32 + mt * 16 + (lane >> 2);
#pragma unroll
        for (int nt = 0; nt < 8; ++nt) {
            int c = col0 + wn * 64 + nt * 8 + (lane & 3) * 2;
            float b0 = 0.0f, b1 = 0.0f;
            if (HASBIAS) { b0 = bias[c]; b1 = bias[c + 1]; }
            float v0 = acc[mt][nt][0] + b0;
            float v1 = acc[mt][nt][1] + b1;
            float v2 = acc[mt][nt][2] + b0;
            float v3 = acc[mt][nt][3] + b1;
            if (ACT) {
                v0 = fmaxf(v0, 0.0f); v1 = fmaxf(v1, 0.0f);
                v2 = fmaxf(v2, 0.0f); v3 = fmaxf(v3, 0.0f);
            }
            *(float2*)&Co[(size_t)r * N + c]       = make_float2(v0, v1);
            *(float2*)&Co[(size_t)(r + 8) * N + c] = make_float2(v2, v3);
        }
    }
}

// ---------------- weight transpose: Wt[n][k] = W[k][n] ----------------
__global__ void transpose_kernel(const float* __restrict__ W, float* __restrict__ Wt,
                                 int K, int N)
{
    __shared__ float tile[32][33];
    int kb = blockIdx.y * 32, nb = blockIdx.x * 32;
    int tx = threadIdx.x, ty = threadIdx.y;   // 32 x 8
#pragma unroll
    for (int i = 0; i < 32; i += 8) {
        int k = kb + ty + i, n = nb + tx;
        tile[ty + i][tx] = (k < K && n < N) ? W[(size_t)k * N + n] : 0.0f;
    }
    __syncthreads();
#pragma unroll
    for (int i = 0; i < 32; i += 8) {
        int n = nb + ty + i, k = kb + tx;
        if (n < N && k < K) Wt[(size_t)n * K + k] = tile[tx][ty + i];
    }
}

// ---------------- small kernels ----------------
__global__ void csq_kernel(const float* __restrict__ cb) {
    int k = blockIdx.x * 256 + threadIdx.x;
    const float4* c = (const float4*)cb + k * 16;
    float s = 0.0f;
#pragma unroll
    for (int i = 0; i < 16; ++i) {
        float4 v = c[i];
        s += v.x * v.x + v.y * v.y + v.z * v.z + v.w * v.w;
    }
    g_csq[k] = s;
}

// combine split-K partials + bias, emit mean/logvar and z_e
__global__ void reparam_kernel(const float* __restrict__ eps,
                               const float* __restrict__ be3,
                               float* __restrict__ out) {
    int i = blockIdx.x * 256 + threadIdx.x;
    if (i >= T_ * D_) return;
    int t = i >> 6, d = i & 63;
    float m  = be3[d]      + g_encp[t * ENC_ + d]      + g_encp[T_*ENC_ + t * ENC_ + d];
    float lv = be3[64 + d] + g_encp[t * ENC_ + 64 + d] + g_encp[T_*ENC_ + t * ENC_ + 64 + d];
    float zv = m + expf(0.5f * lv) * eps[i];
    g_ze[i] = zv;
    out[OUT_MEAN + i] = m;
    out[OUT_LV + i]   = lv;
}

// warp per token: argmin over 1024 codes of (c_sq - 2*cross), gather, per-token loss
__global__ __launch_bounds__(256) void argmin_kernel(const float* __restrict__ cb) {
    int t    = (blockIdx.x * 256 + threadIdx.x) >> 5;
    int lane = threadIdx.x & 31;

    const float4* cr = (const float4*)g_cross + (size_t)t * 256;
    const float4* cq = (const float4*)g_csq;

    float best = 3.4e38f;
    int bestk = 0;
#pragma unroll
    for (int i = 0; i < 8; ++i) {
        int v = lane + i * 32;
        float4 c = cr[v];
        float4 q = cq[v];
        float s0 = q.x - 2.0f * c.x;
        float s1 = q.y - 2.0f * c.y;
        float s2 = q.z - 2.0f * c.z;
        float s3 = q.w - 2.0f * c.w;
        int kb = v * 4;
        if (s0 < best) { best = s0; bestk = kb;     }
        if (s1 < best) { best = s1; bestk = kb + 1; }
        if (s2 < best) { best = s2; bestk = kb + 2; }
        if (s3 < best) { best = s3; bestk = kb + 3; }
    }
#pragma unroll
    for (int off = 16; off; off >>= 1) {
        float ob = __shfl_down_sync(0xffffffffu, best, off);
        int   ok = __shfl_down_sync(0xffffffffu, bestk, off);
        if (ob < best || (ob == best && ok < bestk)) { best = ob; bestk = ok; }
    }
    bestk = __shfl_sync(0xffffffffu, bestk, 0);

    float l = 0.0f;
    if (lane < 16) {
        float4 cv = ((const float4*)cb)[bestk * 16 + lane];
        float4 zv = ((const float4*)g_ze)[t * 16 + lane];
        ((float4*)g_zq)[t * 16 + lane] = cv;
        float dx = zv.x - cv.x, dy = zv.y - cv.y;
        float dz = zv.z - cv.z, dw = zv.w - cv.w;
        l = dx * dx + dy * dy + dz * dz + dw * dw;
    }
#pragma unroll
    for (int off = 16; off; off >>= 1)
        l += __shfl_down_sync(0xffffffffu, l, off);
    if (lane == 0) g_tokloss[t] = l;
}

__global__ __launch_bounds__(256) void dec1_part_kernel(const float* __restrict__ W) {
    __shared__ __align__(16) float zs[256 * 16];
    int k0 = blockIdx.x * 256;
    for (int i = threadIdx.x; i < 4096; i += 256) {
        int b = i >> 8, kk = i & 255;
        zs[kk * 16 + b] = g_zq[b * SD_ + k0 + kk];
    }
    __syncthreads();

    int n = threadIdx.x;
    u64 acc[8];
#pragma unroll
    for (int b2 = 0; b2 < 8; ++b2) acc[b2] = 0ULL;

#pragma unroll 4
    for (int kk = 0; kk < 256; ++kk) {
        u64 wd = dupf(W[(size_t)(k0 + kk) * H2_ + n]);
        const ulonglong2* dk = (const ulonglong2*)(zs + kk * 16);
        ulonglong2 p0 = dk[0], p1 = dk[1], p2 = dk[2], p3 = dk[3];
        u64 dp[8] = {p0.x, p0.y, p1.x, p1.y, p2.x, p2.y, p3.x, p3.y};
#pragma unroll
        for (int b2 = 0; b2 < 8; ++b2) ffma2(acc[b2], dp[b2], wd);
    }
#pragma unroll
    for (int b2 = 0; b2 < 8; ++b2) {
        float2 f = unpk(acc[b2]);
        g_dpart[blockIdx.x * 4096 + (2*b2)   * H2_ + n] = f.x;
        g_dpart[blockIdx.x * 4096 + (2*b2+1) * H2_ + n] = f.y;
    }
}

__global__ void dec1_fin_kernel(const float* __restrict__ bias) {
    int n = blockIdx.x * 256 + threadIdx.x;
    float s = 0.0f;
    for (int c = 0; c < DEC1_CHUNKS; ++c) s += g_dpart[c * 4096 + n];
    g_dvec[n] = fmaxf(s + bias[n & 255], 0.0f);
}

__global__ void vqloss_kernel(float* __restrict__ out) {
    __shared__ float sb[256];
    float a = 0.0f;
    for (int i = threadIdx.x; i < T_; i += 256) a += g_tokloss[i];
    sb[threadIdx.x] = a;
    __syncthreads();
    for (int s = 128; s > 0; s >>= 1) {
        if (threadIdx.x < s) sb[threadIdx.x] += sb[threadIdx.x + s];
        __syncthreads();
    }
    if (threadIdx.x == 0) out[OUT_VQL] = sb[0] / (float)(T_ * D_);
}

__global__ __launch_bounds__(256, 2) void dec2_kernel(
    const float* __restrict__ W, const float* __restrict__ bias,
    float* __restrict__ out)
{
    __shared__ __align__(16) float ds[H2_ * 16];
    for (int i = threadIdx.x; i < 4096; i += 256) {
        int b = i >> 8, k = i & 255;
        ds[k * 16 + b] = g_dvec[i];
    }
    __syncthreads();

    int n = (blockIdx.x * 256 + threadIdx.x) * 4;
    if (n >= SF_) return;

    u64 acc[8][4];
#pragma unroll
    for (int b2 = 0; b2 < 8; ++b2)
#pragma unroll
        for (int c = 0; c < 4; ++c) acc[b2][c] = 0ULL;

#pragma unroll 4
    for (int k = 0; k < H2_; ++k) {
        float4 w = *(const float4*)(W + (size_t)k * SF_ + n);
        u64 wd[4] = {dupf(w.x), dupf(w.y), dupf(w.z), dupf(w.w)};
        const ulonglong2* dk = (const ulonglong2*)(ds + k * 16);
        ulonglong2 p0 = dk[0], p1 = dk[1], p2 = dk[2], p3 = dk[3];
        u64 dp[8] = {p0.x, p0.y, p1.x, p1.y, p2.x, p2.y, p3.x, p3.y};
#pragma unroll
        for (int b2 = 0; b2 < 8; ++b2)
#pragma unroll
            for (int c = 0; c < 4; ++c)
                ffma2(acc[b2][c], dp[b2], wd[c]);
    }

    float4 bb = *(const float4*)(bias + n);
#pragma unroll
    for (int b2 = 0; b2 < 8; ++b2) {
        float2 f0 = unpk(acc[b2][0]);
        float2 f1 = unpk(acc[b2][1]);
        float2 f2 = unpk(acc[b2][2]);
        float2 f3 = unpk(acc[b2][3]);
        float4 v0, v1;
        v0.x = softplusf(f0.x + bb.x);
        v0.y = softplusf(f1.x + bb.y);
        v0.z = softplusf(f2.x + bb.z);
        v0.w = softplusf(f3.x + bb.w);
        v1.x = softplusf(f0.y + bb.x);
        v1.y = softplusf(f1.y + bb.y);
        v1.z = softplusf(f2.y + bb.z);
        v1.w = softplusf(f3.y + bb.w);
        *(float4*)(out + (size_t)(2*b2)   * SF_ + n) = v0;
        *(float4*)(out + (size_t)(2*b2+1) * SF_ + n) = v1;
    }
}

// ---------------- launch ----------------
extern "C" void kernel_launch(void* const* d_in, const int* in_sizes, int n_in,
                              void* d_out, int out_size)
{
    const float* x   = (const float*)d_in[0];
    const float* eps = (const float*)d_in[1];
    const float* We1 = (const float*)d_in[2];
    const float* be1 = (const float*)d_in[3];
    const float* We2 = (const float*)d_in[4];
    const float* be2 = (const float*)d_in[5];
    const float* We3 = (const float*)d_in[6];
    const float* be3 = (const float*)d_in[7];
    const float* cb  = (const float*)d_in[8];
    const float* Wd1 = (const float*)d_in[9];
    const float* bd1 = (const float*)d_in[10];
    const float* Wd2 = (const float*)d_in[11];
    const float* bd2 = (const float*)d_in[12];
    float* out = (float*)d_out;

    void *p_h1, *p_h2, *p_encp, *p_ze, *p_cross, *p_wt1, *p_wt2, *p_wt3;
    cudaGetSymbolAddress(&p_h1,    g_h1);
    cudaGetSymbolAddress(&p_h2,    g_h2);
    cudaGetSymbolAddress(&p_encp,  g_encp);
    cudaGetSymbolAddress(&p_ze,    g_ze);
    cudaGetSymbolAddress(&p_cross, g_cross);
    cudaGetSymbolAddress(&p_wt1,   g_wt1);
    cudaGetSymbolAddress(&p_wt2,   g_wt2);
    cudaGetSymbolAddress(&p_wt3,   g_wt3);

    cudaFuncSetAttribute(mma_gemm<1,1,0>, cudaFuncAttributeMaxDynamicSharedMemorySize, SMEM_BYTES);
    cudaFuncSetAttribute(mma_gemm<0,0,0>, cudaFuncAttributeMaxDynamicSharedMemorySize, SMEM_BYTES);
    cudaFuncSetAttribute(mma_gemm<0,0,1>, cudaFuncAttributeMaxDynamicSharedMemorySize, SMEM_BYTES);

    // weight transposes (K-major operands)
    transpose_kernel<<<dim3(16, 22), dim3(32, 8)>>>(We1, (float*)p_wt1, F_,  H1_);
    transpose_kernel<<<dim3(8, 16),  dim3(32, 8)>>>(We2, (float*)p_wt2, H1_, H2_);
    transpose_kernel<<<dim3(4, 8),   dim3(32, 8)>>>(We3, (float*)p_wt3, H2_, ENC_);
    csq_kernel<<<4, 256>>>(cb);

    // encoder MLP on tensor cores (bf16x3 split precision)
    mma_gemm<1,1,0><<<dim3(4, 72), 256, SMEM_BYTES>>>(T_, H1_, F_,  0,
        x,            (float*)p_wt1, be1, (float*)p_h1);
    mma_gemm<1,1,0><<<dim3(2, 72), 256, SMEM_BYTES>>>(T_, H2_, H1_, 0,
        (float*)p_h1, (float*)p_wt2, be2, (float*)p_h2);
    mma_gemm<0,0,1><<<dim3(1, 72, ZSPLIT), 256, SMEM_BYTES>>>(T_, ENC_, H2_, H2_/ZSPLIT,
        (float*)p_h2, (float*)p_wt3, nullptr, (float*)p_encp);

    reparam_kernel<<<(T_ * D_ + 255) / 256, 256>>>(eps, be3, out);

    // VQ cross = z_e @ codebook^T (codebook already [N][K] K-major)
    mma_gemm<0,0,0><<<dim3(8, 72), 256, SMEM_BYTES>>>(T_, KC_, D_, 0,
        (float*)p_ze, cb, nullptr, (float*)p_cross);
    argmin_kernel<<<T_ / 8, 256>>>(cb);

    // decoder
    dec1_part_kernel<<<DEC1_CHUNKS, 256>>>(Wd1);
    dec1_fin_kernel<<<16, 256>>>(bd1);
    vqloss_kernel<<<1, 256>>>(out);
    dec2_kernel<<<(SF_ / 4 + 255) / 256, 256>>>(Wd2, bd2, out);
}